// round 14
// baseline (speedup 1.0000x reference)
#include <cuda_runtime.h>
#include <cuda_fp16.h>
#include <cstdint>

// ---------------------------------------------------------------------------
// InterleavedHeadAttention — round 14
//   - attention: warp-specialized (1 producer + 8 consumer warps) with
//     mbarrier FULL / EMPTY ring (sm_80 primitives) — consumers decoupled
//     from each other so softmax windows stagger across warps.
//   - gemmA / gemmO / prep unchanged from round 13.
//   B=2, S=1024, HID=1024, H=16, P=2, D=64, sv=2048
// ---------------------------------------------------------------------------

#define NB 2
#define SEQ 1024
#define HIDD 1024
#define NH 16
#define NP 2
#define HD 64
#define SVLEN (SEQ * NP)        // 2048
#define MTOK (NB * SEQ)         // 2048
#define NPROJ (NH * NP * HD)    // 2048
#define ATTN_SCALE 0.125f
#define LOG2E 1.4426950408889634f

#define NEG_INF __int_as_float(0xff800000)

// fp16 storage, all natural layouts
__device__ __half g_Weff[3][NPROJ][HIDD];
__device__ __half g_Woeff[HIDD][NPROJ];      // [f][o*64+d]
__device__ __half g_Xr[MTOK][HIDD];
__device__ __half g_Q[NB * NH][SVLEN][HD];
__device__ __half g_K[NB * NH][SVLEN][HD];
__device__ __half g_Vt[NB * NH][HD][SVLEN];  // transposed
__device__ __half g_Aout[NB * NH][SVLEN][HD];

// ---------------------------------------------------------------------------
// helpers
// ---------------------------------------------------------------------------
__device__ __forceinline__ void cp16(uint32_t s, const void* g) {
    asm volatile("cp.async.cg.shared.global [%0], [%1], 16;" :: "r"(s), "l"(g));
}
__device__ __forceinline__ uint32_t smem_u32(const void* p) {
    uint32_t a;
    asm("{ .reg .u64 t; cvta.to.shared.u64 t, %1; cvt.u32.u64 %0, t; }"
        : "=r"(a) : "l"(p));
    return a;
}
#define CP_COMMIT() asm volatile("cp.async.commit_group;" ::: "memory")
#define CP_WAIT(n)  asm volatile("cp.async.wait_group %0;" :: "n"(n) : "memory")

__device__ __forceinline__ void mbar_init(uint32_t a, uint32_t cnt) {
    asm volatile("mbarrier.init.shared.b64 [%0], %1;" :: "r"(a), "r"(cnt) : "memory");
}
__device__ __forceinline__ void mbar_arrive(uint32_t a) {
    asm volatile("{\n\t.reg .b64 t;\n\tmbarrier.arrive.shared.b64 t, [%0];\n\t}"
                 :: "r"(a) : "memory");
}
__device__ __forceinline__ void cpam_noinc(uint32_t a) {
    asm volatile("cp.async.mbarrier.arrive.noinc.shared.b64 [%0];"
                 :: "r"(a) : "memory");
}
__device__ __forceinline__ void mbar_wait(uint32_t a, uint32_t parity) {
    uint32_t done = 0;
    while (!done) {
        asm volatile("{\n\t.reg .pred p;\n\t"
                     "mbarrier.test_wait.parity.shared.b64 p, [%1], %2;\n\t"
                     "selp.b32 %0, 1, 0, p;\n\t}"
                     : "=r"(done) : "r"(a), "r"(parity) : "memory");
    }
}

__device__ __forceinline__ void st_h2(__half* p, float a, float b) {
    *(__half2*)p = __float22half2_rn(make_float2(a, b));
}
__device__ __forceinline__ uint32_t pack_h2(float a, float b) {
    __half2 h = __float22half2_rn(make_float2(a, b));
    return *(uint32_t*)&h;
}
__device__ __forceinline__ float ex2(float x) {
    float r;
    asm("ex2.approx.f32 %0, %1;" : "=f"(r) : "f"(x));
    return r;
}
__device__ __forceinline__ void mma_f16(float* c, const uint32_t* a,
                                        const uint32_t* b) {
    asm volatile(
        "mma.sync.aligned.m16n8k16.row.col.f32.f16.f16.f32 "
        "{%0,%1,%2,%3}, {%4,%5,%6,%7}, {%8,%9}, {%0,%1,%2,%3};"
        : "+f"(c[0]), "+f"(c[1]), "+f"(c[2]), "+f"(c[3])
        : "r"(a[0]), "r"(a[1]), "r"(a[2]), "r"(a[3]), "r"(b[0]), "r"(b[1]));
}
__device__ __forceinline__ void ldsm_x4(uint32_t& r0, uint32_t& r1,
                                        uint32_t& r2, uint32_t& r3, uint32_t a) {
    asm volatile("ldmatrix.sync.aligned.m8n8.x4.shared.b16 {%0,%1,%2,%3}, [%4];"
                 : "=r"(r0), "=r"(r1), "=r"(r2), "=r"(r3) : "r"(a));
}

// ---------------------------------------------------------------------------
// Fused prologue: y=0..2 build_weff(q/k/v), y=3 build_woeff, y=4 round_x.
// ---------------------------------------------------------------------------
__global__ __launch_bounds__(256) void prep_k(
    const float* __restrict__ x,
    const float* __restrict__ Wq, const float* __restrict__ Wk,
    const float* __restrict__ Wv, const float* __restrict__ Wo,
    const float* __restrict__ aq, const float* __restrict__ ak,
    const float* __restrict__ av, const float* __restrict__ cl)
{
    __shared__ float sS[512];
    const int tid = threadIdx.x;
    const int y = blockIdx.y;

    if (y < 3) {
        const float* W = (y == 0) ? Wq : (y == 1) ? Wk : Wv;
        const float* A = (y == 0) ? aq : (y == 1) ? ak : av;
        sS[tid] = A[tid];
        sS[tid + 256] = A[tid + 256];
        __syncthreads();
        int idx = blockIdx.x * 256 + tid;       // over 64*1024
        int d = idx >> 10, e = idx & 1023;
        float wv[NH];
#pragma unroll
        for (int m = 0; m < NH; m++)
            wv[m] = W[(m * HD + d) * HIDD + e];
        float scale = (y == 0) ? ATTN_SCALE * LOG2E : 1.0f;
#pragma unroll
        for (int hp = 0; hp < 32; hp++) {
            float acc = 0.f;
#pragma unroll
            for (int m = 0; m < NH; m++)
                acc += sS[m * 32 + hp] * wv[m];
            g_Weff[y][hp * HD + d][e] = __float2half_rn(acc * scale);
        }
    } else if (y == 3) {
        sS[tid] = cl[tid];
        sS[tid + 256] = cl[tid + 256];
        __syncthreads();
        int idx = blockIdx.x * 256 + tid;       // over 1024*64
        int f = idx >> 6, d = idx & 63;
        float wv[NH];
#pragma unroll
        for (int h = 0; h < NH; h++)
            wv[h] = Wo[f * HIDD + h * HD + d];
#pragma unroll
        for (int o = 0; o < 32; o++) {
            float acc = 0.f;
#pragma unroll
            for (int h = 0; h < NH; h++)
                acc += sS[h * 32 + o] * wv[h];
            g_Woeff[f][o * HD + d] = __float2half_rn(acc);
        }
    } else {
        const float4* x4 = (const float4*)x;
        uint2* dst = (uint2*)&g_Xr[0][0];
#pragma unroll
        for (int it = 0; it < 8; it++) {
            int idx4 = it * 65536 + blockIdx.x * 256 + tid;
            float4 v = x4[idx4];
            uint2 o;
            o.x = pack_h2(v.x, v.y);
            o.y = pack_h2(v.z, v.w);
            dst[idx4] = o;
        }
    }
}

// ---------------------------------------------------------------------------
// gemmA smem tiles: rows of 64 halves (128B), XOR chunk swizzle
// ---------------------------------------------------------------------------
#define G_TILEB 16384
#define G_STGB (2 * G_TILEB)
#define NSTG 3
#define SMEM_G (NSTG * G_STGB)           // 96 KB

// ---------------------------------------------------------------------------
// Projection GEMM (fp16): C[2048,2048] = Xr * Weff[z]^T, K=1024.
// ---------------------------------------------------------------------------
__global__ __launch_bounds__(256, 2) void gemmA_k()
{
    extern __shared__ __align__(16) char smc[];
    const int tid = threadIdx.x, wid = tid >> 5, lane = tid & 31;
    const int wm = (wid & 3) * 32;
    const int wn = (wid >> 2) * 64;
    const int bn = blockIdx.x * 128, bm = blockIdx.y * 128;
    const int which = blockIdx.z;
    const __half* Aw = &g_Xr[0][0];
    const __half* Bw = &g_Weff[which][0][0];
    const uint32_t sb = smem_u32(smc);
    const int fr = lane >> 2, fc = lane & 3;
    const int lrow = tid >> 1;
    const int cb = (tid & 1) * 4;

    const int li = lane & 7;
    const int g8 = (lane >> 3) & 1, g16 = lane >> 4;
    uint32_t rowOffA[2]; int rmA[2];
#pragma unroll
    for (int mt = 0; mt < 2; mt++) {
        int r = wm + mt * 16 + g8 * 8 + li;
        rowOffA[mt] = (uint32_t)r * 128; rmA[mt] = r & 7;
    }
    uint32_t rowOffB[4]; int rmB[4];
#pragma unroll
    for (int j = 0; j < 4; j++) {
        int r = wn + j * 16 + g16 * 8 + li;
        rowOffB[j] = (uint32_t)r * 128; rmB[j] = r & 7;
    }

    auto issue = [&](int kc) {
        int s = kc % NSTG;
        int k0 = kc * 64;
        uint32_t sa = sb + (uint32_t)s * G_STGB;
        uint32_t sbB = sa + G_TILEB;
        uint32_t dstrow = (uint32_t)lrow * 128;
        int swm = lrow & 7;
        const __half* asrc = Aw + (size_t)(bm + lrow) * HIDD + k0;
        const __half* bsrc = Bw + (size_t)(bn + lrow) * HIDD + k0;
#pragma unroll
        for (int c = 0; c < 4; c++) {
            int cc = cb + c;
            uint32_t off = dstrow + (uint32_t)((cc ^ swm) << 4);
            cp16(sa + off, asrc + cc * 8);
            cp16(sbB + off, bsrc + cc * 8);
        }
    };

    float acc[2][8][4];
#pragma unroll
    for (int mt = 0; mt < 2; mt++)
#pragma unroll
        for (int nt = 0; nt < 8; nt++)
#pragma unroll
            for (int j = 0; j < 4; j++) acc[mt][nt][j] = 0.f;

    issue(0); CP_COMMIT();
    issue(1); CP_COMMIT();

    const int NKC = HIDD / 64;
    for (int kc = 0; kc < NKC; kc++) {
        CP_WAIT(1);
        __syncthreads();
        if (kc + 2 < NKC) issue(kc + 2);
        CP_COMMIT();
        uint32_t Ab = sb + (uint32_t)(kc % NSTG) * G_STGB;
        uint32_t Bb = Ab + G_TILEB;
#pragma unroll
        for (int k16 = 0; k16 < 4; k16++) {
            uint32_t afr[2][4], bfr[8][2];
#pragma unroll
            for (int mt = 0; mt < 2; mt++) {
                uint32_t a = Ab + rowOffA[mt] +
                    (uint32_t)((((2 * k16) + g16) ^ rmA[mt]) << 4);
                ldsm_x4(afr[mt][0], afr[mt][1], afr[mt][2], afr[mt][3], a);
            }
#pragma unroll
            for (int j = 0; j < 4; j++) {
                uint32_t a = Bb + rowOffB[j] +
                    (uint32_t)((((2 * k16) + g8) ^ rmB[j]) << 4);
                ldsm_x4(bfr[2 * j][0], bfr[2 * j][1],
                        bfr[2 * j + 1][0], bfr[2 * j + 1][1], a);
            }
#pragma unroll
            for (int mt = 0; mt < 2; mt++)
#pragma unroll
                for (int nt = 0; nt < 8; nt++)
                    mma_f16(acc[mt][nt], afr[mt], bfr[nt]);
        }
    }

    // ---- epilogue (natural layouts) ----
    if (which == 2) {
        int h = bn >> 7, p = (wn >> 6) & 1;
#pragma unroll
        for (int mt = 0; mt < 2; mt++) {
#pragma unroll
            for (int half_ = 0; half_ < 2; half_++) {
                int row = bm + wm + mt * 16 + fr + half_ * 8;
                int b = row >> 10, n = row & 1023;
                int kv = n * NP + p;
                __half* Vt = &g_Vt[b * NH + h][0][0];
#pragma unroll
                for (int nt = 0; nt < 8; nt++) {
                    int d = nt * 8 + 2 * fc;
                    Vt[(size_t)d * SVLEN + kv] =
                        __float2half_rn(acc[mt][nt][half_ * 2 + 0]);
                    Vt[(size_t)(d + 1) * SVLEN + kv] =
                        __float2half_rn(acc[mt][nt][half_ * 2 + 1]);
                }
            }
        }
    } else {
        __half* dst0 = (which == 0) ? &g_Q[0][0][0] : &g_K[0][0][0];
#pragma unroll
        for (int mt = 0; mt < 2; mt++) {
#pragma unroll
            for (int half_ = 0; half_ < 2; half_++) {
                int row = bm + wm + mt * 16 + fr + half_ * 8;
                int b = row >> 10, n = row & 1023;
#pragma unroll
                for (int nt = 0; nt < 8; nt++) {
                    int col = bn + wn + nt * 8 + 2 * fc;
                    int h = col >> 7, p = (col >> 6) & 1, d = col & 63;
                    __half* dst = dst0 +
                        ((size_t)(b * NH + h) * SVLEN + n * NP + p) * HD + d;
                    st_h2(dst, acc[mt][nt][half_ * 2 + 0],
                               acc[mt][nt][half_ * 2 + 1]);
                }
            }
        }
    }
}

// ---------------------------------------------------------------------------
// Output GEMM (fp16): out[2048,1024] = gather(g_Aout) * Woeff^T, K=2048.
//   CTA 64x128, KC=128, NSTG=2, depth-1 prefetch, 256 CTAs.
// ---------------------------------------------------------------------------
#define O_AB 16384
#define O_BB 32768
#define O_STGB (O_AB + O_BB)
#define SMEM_O (2 * O_STGB)              // 96 KB

__global__ __launch_bounds__(256, 2) void gemmO_k(float* __restrict__ Cout)
{
    extern __shared__ __align__(16) char smc[];
    const int tid = threadIdx.x, wid = tid >> 5, lane = tid & 31;
    const int wm = (wid & 1) * 32;
    const int wn = (wid >> 1) * 32;
    const int bn = blockIdx.x * 128, bm = blockIdx.y * 64;
    const __half* Bw = &g_Woeff[0][0];
    const uint32_t sb = smem_u32(smc);
    const int fr = lane >> 2, fc = lane & 3;

    const int li = lane & 7;
    const int g8 = (lane >> 3) & 1, g16 = lane >> 4;
    uint32_t rowOffA[2]; int rmA[2];
#pragma unroll
    for (int mt = 0; mt < 2; mt++) {
        int r = wm + mt * 16 + g8 * 8 + li;
        rowOffA[mt] = (uint32_t)r * 256; rmA[mt] = r & 7;
    }
    uint32_t rowOffB[2]; int rmB[2];
#pragma unroll
    for (int j = 0; j < 2; j++) {
        int r = wn + j * 16 + g16 * 8 + li;
        rowOffB[j] = (uint32_t)r * 256; rmB[j] = r & 7;
    }

    const int arow = tid >> 2;
    const int ab2 = (tid & 3) * 2;
    const int brow = tid >> 1;
    const int bb4 = (tid & 1) * 4;

    int ta = bm + arow;
    int gb = ta >> 10, gn = ta & 1023;

    auto issue = [&](int kc) {
        int s = kc & 1;
        int k0 = kc * 128;
        uint32_t sa = sb + (uint32_t)s * O_STGB;
        uint32_t sbB = sa + O_AB;
        {
            uint32_t dstrow = (uint32_t)arow * 256;
            int swm = arow & 7;
#pragma unroll
            for (int c = 0; c < 4; c++) {
                int cc = ab2 + (c & 1) + (c >> 1) * 8;
                uint32_t off = dstrow + (uint32_t)((cc ^ swm) << 4);
                int col = k0 + cc * 8;
                int o = col >> 6, dd = col & 63;
                cp16(sa + off,
                     &g_Aout[gb * NH + (o >> 1)][gn * NP + (o & 1)][dd]);
            }
        }
        {
            uint32_t dstrow = (uint32_t)brow * 256;
            int swm = brow & 7;
            const __half* bsrc = Bw + (size_t)(bn + brow) * NPROJ + k0;
#pragma unroll
            for (int c = 0; c < 8; c++) {
                int cc = bb4 + (c & 3) + (c >> 2) * 8;
                uint32_t off = dstrow + (uint32_t)((cc ^ swm) << 4);
                cp16(sbB + off, bsrc + cc * 8);
            }
        }
    };

    float acc[2][4][4];
#pragma unroll
    for (int mt = 0; mt < 2; mt++)
#pragma unroll
        for (int nt = 0; nt < 4; nt++)
#pragma unroll
            for (int j = 0; j < 4; j++) acc[mt][nt][j] = 0.f;

    issue(0); CP_COMMIT();

    const int NKC = NPROJ / 128;   // 16
    for (int kc = 0; kc < NKC; kc++) {
        CP_WAIT(0);
        __syncthreads();
        if (kc + 1 < NKC) issue(kc + 1);
        CP_COMMIT();
        uint32_t Ab = sb + (uint32_t)(kc & 1) * O_STGB;
        uint32_t Bb = Ab + O_AB;
#pragma unroll
        for (int k16 = 0; k16 < 8; k16++) {
            uint32_t afr[2][4], bfr[4][2];
#pragma unroll
            for (int mt = 0; mt < 2; mt++) {
                uint32_t a = Ab + rowOffA[mt] +
                    (uint32_t)((((2 * k16) + g16) ^ rmA[mt]) << 4);
                ldsm_x4(afr[mt][0], afr[mt][1], afr[mt][2], afr[mt][3], a);
            }
#pragma unroll
            for (int j = 0; j < 2; j++) {
                uint32_t a = Bb + rowOffB[j] +
                    (uint32_t)((((2 * k16) + g8) ^ rmB[j]) << 4);
                ldsm_x4(bfr[2 * j][0], bfr[2 * j][1],
                        bfr[2 * j + 1][0], bfr[2 * j + 1][1], a);
            }
#pragma unroll
            for (int mt = 0; mt < 2; mt++)
#pragma unroll
                for (int nt = 0; nt < 4; nt++)
                    mma_f16(acc[mt][nt], afr[mt], bfr[nt]);
        }
    }

#pragma unroll
    for (int mt = 0; mt < 2; mt++) {
#pragma unroll
        for (int half_ = 0; half_ < 2; half_++) {
            int row = bm + wm + mt * 16 + fr + half_ * 8;
#pragma unroll
            for (int nt = 0; nt < 4; nt++) {
                int col = bn + wn + nt * 8 + 2 * fc;
                *(float2*)(Cout + (size_t)row * HIDD + col) = make_float2(
                    acc[mt][nt][half_ * 2 + 0], acc[mt][nt][half_ * 2 + 1]);
            }
        }
    }
}

// ---------------------------------------------------------------------------
// Causal flash attention — warp-specialized, mbarrier ring.
//   288 threads: warps 0-7 consumers (16 q-rows each), warp 8 producer.
//   4-buffer KV ring. FULL[s]: mbarrier count 32 (producer cp.async arrive).
//   EMPTY[s]: mbarrier count 256 (consumer arrives). Consumers poll FULL
//   independently -> no consumer-consumer lockstep.
// ---------------------------------------------------------------------------
#define Q_B 16384
#define KV_B 8192
#define ATTN_NBUF 4
#define MB_OFF (Q_B + ATTN_NBUF * 2 * KV_B)      // 81920
#define SMEM_ATTN (MB_OFF + 128)                 // 82048 B

__global__ __launch_bounds__(288, 2) void attn_k()
{
    extern __shared__ __align__(16) char smc[];
    const uint32_t sQ = smem_u32(smc);
    const uint32_t sKV = sQ + Q_B;
    const uint32_t sMB = sQ + MB_OFF;            // full[s]=+8s, empty[s]=+64+8s

    const int bh = blockIdx.y;
    const int qt = (gridDim.x - 1) - blockIdx.x;   // heavy tiles first
    const int qstart = qt * 128;
    const __half* Qg = &g_Q[bh][0][0];
    const __half* Kg = &g_K[bh][0][0];
    const __half* Vtg = &g_Vt[bh][0][0];

    const int tid = threadIdx.x;
    const int wid = tid >> 5;
    const int lane = tid & 31;
    const int jmax = 2 * qt + 1;

    if (tid == 0) {
#pragma unroll
        for (int s = 0; s < ATTN_NBUF; s++) {
            mbar_init(sMB + 8 * s, 32);           // FULL
            mbar_init(sMB + 64 + 8 * s, 256);     // EMPTY
        }
    }
    __syncthreads();

    if (wid == 8) {
        // ------------------- producer warp -------------------
        const int pt = lane;
        auto issue_kv = [&](int jt) {
            int buf = jt & (ATTN_NBUF - 1);
            uint32_t sK = sKV + (uint32_t)buf * (2 * KV_B);
            uint32_t sV = sK + KV_B;
            int kstart = jt * 64;
#pragma unroll
            for (int it = 0; it < 16; it++) {
                int chunk = pt + 32 * it;          // 512 chunks (K)
                int row = chunk >> 3;
                int cc = chunk & 7;
                uint32_t off = (uint32_t)row * 128 +
                               (uint32_t)((cc ^ (row & 7)) << 4);
                cp16(sK + off, Kg + (size_t)(kstart + row) * HD + cc * 8);
                cp16(sV + off, Vtg + (size_t)row * SVLEN + kstart + cc * 8);
            }
        };
        // Q with tile 0 (same arrive covers both)
#pragma unroll
        for (int it = 0; it < 32; it++) {
            int chunk = pt + 32 * it;              // 1024 chunks
            int row = chunk >> 3;
            int cc = chunk & 7;
            uint32_t off = (uint32_t)row * 128 +
                           (uint32_t)((cc ^ (row & 7)) << 4);
            cp16(sQ + off, Qg + (size_t)(qstart + row) * HD + cc * 8);
        }
        issue_kv(0);
        cpam_noinc(sMB + 0);
        for (int s = 1; s < ATTN_NBUF && s <= jmax; s++) {
            issue_kv(s);
            cpam_noinc(sMB + 8 * s);
        }
        for (int jtn = ATTN_NBUF; jtn <= jmax; jtn++) {
            int buf = jtn & (ATTN_NBUF - 1);
            uint32_t par = (uint32_t)(((jtn - ATTN_NBUF) >> 2) & 1);
            mbar_wait(sMB + 64 + 8 * buf, par);    // consumers done with buf
            issue_kv(jtn);
            cpam_noinc(sMB + 8 * buf);
        }
        return;
    }

    // ------------------- consumer warps (0-7) -------------------
    const int wq = wid;
    const int fr = lane >> 2;
    const int fc = lane & 3;
    const int r0 = wq * 16 + fr, r1 = r0 + 8;

    const int li = lane & 7;
    const int g8 = (lane >> 3) & 1, g16 = lane >> 4;
    const int rowQ = wq * 16 + g8 * 8 + li;
    const uint32_t rowOffQ = (uint32_t)rowQ * 128;
    const int rmQ = rowQ & 7;
    uint32_t rowOffKV[4]; int rmKV[4];
#pragma unroll
    for (int j = 0; j < 4; j++) {
        int r = j * 16 + g16 * 8 + li;
        rowOffKV[j] = (uint32_t)r * 128; rmKV[j] = r & 7;
    }

    float O[8][4];
    float m0 = NEG_INF, m1 = NEG_INF, l0 = 0.f, l1 = 0.f;
#pragma unroll
    for (int nt = 0; nt < 8; nt++)
#pragma unroll
        for (int j = 0; j < 4; j++) O[nt][j] = 0.f;

    uint32_t qfr[4][4];

    for (int jt = 0; jt <= jmax; jt++) {
        const int kstart = jt * 64;
        const int buf = jt & (ATTN_NBUF - 1);
        mbar_wait(sMB + 8 * buf, (uint32_t)((jt >> 2) & 1));   // FULL
        uint32_t Kb = sKV + (uint32_t)buf * (2 * KV_B);
        uint32_t Vb = Kb + KV_B;

        if (jt == 0) {
#pragma unroll
            for (int k16 = 0; k16 < 4; k16++) {
                uint32_t a = sQ + rowOffQ +
                    (uint32_t)((((2 * k16) + g16) ^ rmQ) << 4);
                ldsm_x4(qfr[k16][0], qfr[k16][1], qfr[k16][2], qfr[k16][3], a);
            }
        }

        // ---- S = Q K^T (pre-scaled by scale*log2e) ----
        float s[8][4];
#pragma unroll
        for (int nt = 0; nt < 8; nt++)
#pragma unroll
            for (int j = 0; j < 4; j++) s[nt][j] = 0.f;
#pragma unroll
        for (int k16 = 0; k16 < 4; k16++) {
            uint32_t bfr[8][2];
#pragma unroll
            for (int j = 0; j < 4; j++) {
                uint32_t a = Kb + rowOffKV[j] +
                    (uint32_t)((((2 * k16) + g8) ^ rmKV[j]) << 4);
                ldsm_x4(bfr[2 * j][0], bfr[2 * j][1],
                        bfr[2 * j + 1][0], bfr[2 * j + 1][1], a);
            }
#pragma unroll
            for (int nt = 0; nt < 8; nt++)
                mma_f16(s[nt], qfr[k16], bfr[nt]);
        }

        // causal mask
        if (kstart + 63 > qstart + wq * 16) {
            int gr0 = qstart + r0, gr1 = gr0 + 8;
#pragma unroll
            for (int nt = 0; nt < 8; nt++) {
                int c0 = kstart + nt * 8 + 2 * fc;
                if (c0 > gr0)     s[nt][0] = NEG_INF;
                if (c0 + 1 > gr0) s[nt][1] = NEG_INF;
                if (c0 > gr1)     s[nt][2] = NEG_INF;
                if (c0 + 1 > gr1) s[nt][3] = NEG_INF;
            }
        }

        // ---- online softmax in log2 domain ----
        float mx0 = NEG_INF, mx1 = NEG_INF;
#pragma unroll
        for (int nt = 0; nt < 8; nt++) {
            mx0 = fmaxf(mx0, fmaxf(s[nt][0], s[nt][1]));
            mx1 = fmaxf(mx1, fmaxf(s[nt][2], s[nt][3]));
        }
        mx0 = fmaxf(mx0, __shfl_xor_sync(0xffffffffu, mx0, 1));
        mx0 = fmaxf(mx0, __shfl_xor_sync(0xffffffffu, mx0, 2));
        mx1 = fmaxf(mx1, __shfl_xor_sync(0xffffffffu, mx1, 1));
        mx1 = fmaxf(mx1, __shfl_xor_sync(0xffffffffu, mx1, 2));
        float newm0 = fmaxf(m0, mx0), newm1 = fmaxf(m1, mx1);
        float al0 = ex2(m0 - newm0), al1 = ex2(m1 - newm1);

        uint32_t pfr[4][4];
        float rs0 = 0.f, rs1 = 0.f;
#pragma unroll
        for (int nt = 0; nt < 8; nt++) {
            float p0 = ex2(s[nt][0] - newm0);
            float p1 = ex2(s[nt][1] - newm0);
            float p2 = ex2(s[nt][2] - newm1);
            float p3 = ex2(s[nt][3] - newm1);
            rs0 += p0 + p1; rs1 += p2 + p3;
            int t16 = nt >> 1, hi = nt & 1;
            pfr[t16][hi * 2 + 0] = pack_h2(p0, p1);   // row r0
            pfr[t16][hi * 2 + 1] = pack_h2(p2, p3);   // row r1
        }
        rs0 += __shfl_xor_sync(0xffffffffu, rs0, 1);
        rs0 += __shfl_xor_sync(0xffffffffu, rs0, 2);
        rs1 += __shfl_xor_sync(0xffffffffu, rs1, 1);
        rs1 += __shfl_xor_sync(0xffffffffu, rs1, 2);
        l0 = l0 * al0 + rs0; l1 = l1 * al1 + rs1;
        m0 = newm0; m1 = newm1;
#pragma unroll
        for (int nt = 0; nt < 8; nt++) {
            O[nt][0] *= al0; O[nt][1] *= al0;
            O[nt][2] *= al1; O[nt][3] *= al1;
        }

        // ---- O += P V ----
#pragma unroll
        for (int k16 = 0; k16 < 4; k16++) {
            uint32_t bfr[8][2];
#pragma unroll
            for (int j = 0; j < 4; j++) {
                uint32_t a = Vb + rowOffKV[j] +
                    (uint32_t)((((2 * k16) + g8) ^ rmKV[j]) << 4);
                ldsm_x4(bfr[2 * j][0], bfr[2 * j][1],
                        bfr[2 * j + 1][0], bfr[2 * j + 1][1], a);
            }
#pragma unroll
            for (int nt = 0; nt < 8; nt++)
                mma_f16(O[nt], pfr[k16], bfr[nt]);
        }
        mbar_arrive(sMB + 64 + 8 * buf);   // done reading buf (LDSM ordered)
    }

    // epilogue: normalize, store natural fp16 into g_Aout
    __half* Ag = &g_Aout[bh][0][0];
    float inv0 = 1.f / l0, inv1 = 1.f / l1;
#pragma unroll
    for (int nt = 0; nt < 8; nt++) {
        int pos = nt * 8 + 2 * fc;
        st_h2(Ag + (size_t)(qstart + r0) * HD + pos,
              O[nt][0] * inv0, O[nt][1] * inv0);
        st_h2(Ag + (size_t)(qstart + r1) * HD + pos,
              O[nt][2] * inv1, O[nt][3] * inv1);
    }
}

// ---------------------------------------------------------------------------
// launch
// ---------------------------------------------------------------------------
extern "C" void kernel_launch(void* const* d_in, const int* in_sizes, int n_in,
                              void* d_out, int out_size)
{
    const float* x  = (const float*)d_in[0];
    const float* Wq = (const float*)d_in[1];
    const float* Wk = (const float*)d_in[2];
    const float* Wv = (const float*)d_in[3];
    const float* Wo = (const float*)d_in[4];
    const float* aq = (const float*)d_in[5];
    const float* ak = (const float*)d_in[6];
    const float* av = (const float*)d_in[7];
    const float* cl = (const float*)d_in[8];
    float* out = (float*)d_out;

    cudaFuncSetAttribute(gemmA_k, cudaFuncAttributeMaxDynamicSharedMemorySize, SMEM_G);
    cudaFuncSetAttribute(gemmO_k, cudaFuncAttributeMaxDynamicSharedMemorySize, SMEM_O);
    cudaFuncSetAttribute(attn_k, cudaFuncAttributeMaxDynamicSharedMemorySize, SMEM_ATTN);

    // fused prologue: weight builds + x rounding, all concurrent
    prep_k<<<dim3(256, 5), 256>>>(x, Wq, Wk, Wv, Wo, aq, ak, av, cl);

    // projections + head mixing (q/k/v via z)
    gemmA_k<<<dim3(NPROJ / 128, MTOK / 128, 3), 256, SMEM_G>>>();

    // causal SDPA over virtual positions (warp-specialized)
    attn_k<<<dim3(SVLEN / 128, NB * NH), 288, SMEM_ATTN>>>();

    // collapse + output projection (256 CTAs, KC=128)
    gemmO_k<<<dim3(HIDD / 128, MTOK / 64), 256, SMEM_O>>>(out);
}

// round 15
// speedup vs baseline: 1.0052x; 1.0052x over previous
#include <cuda_runtime.h>
#include <cuda_fp16.h>
#include <cstdint>

// ---------------------------------------------------------------------------
// InterleavedHeadAttention — round 15
//   - attention reverted to round-13 form (warp-specialization falsified)
//   - gemmO: split-K=2 with gemmA's proven CTA 128x128 / warp 32x64 layout,
//     f32 atomicAdd epilogue into pre-zeroed out (2 contributors -> exact)
//   B=2, S=1024, HID=1024, H=16, P=2, D=64, sv=2048
// ---------------------------------------------------------------------------

#define NB 2
#define SEQ 1024
#define HIDD 1024
#define NH 16
#define NP 2
#define HD 64
#define SVLEN (SEQ * NP)        // 2048
#define MTOK (NB * SEQ)         // 2048
#define NPROJ (NH * NP * HD)    // 2048
#define ATTN_SCALE 0.125f
#define LOG2E 1.4426950408889634f

#define NEG_INF __int_as_float(0xff800000)

// fp16 storage, all natural layouts
__device__ __half g_Weff[3][NPROJ][HIDD];
__device__ __half g_Woeff[HIDD][NPROJ];      // [f][o*64+d]
__device__ __half g_Xr[MTOK][HIDD];
__device__ __half g_Q[NB * NH][SVLEN][HD];
__device__ __half g_K[NB * NH][SVLEN][HD];
__device__ __half g_Vt[NB * NH][HD][SVLEN];  // transposed
__device__ __half g_Aout[NB * NH][SVLEN][HD];

// ---------------------------------------------------------------------------
// helpers
// ---------------------------------------------------------------------------
__device__ __forceinline__ void cp16(uint32_t s, const void* g) {
    asm volatile("cp.async.cg.shared.global [%0], [%1], 16;" :: "r"(s), "l"(g));
}
__device__ __forceinline__ uint32_t smem_u32(const void* p) {
    uint32_t a;
    asm("{ .reg .u64 t; cvta.to.shared.u64 t, %1; cvt.u32.u64 %0, t; }"
        : "=r"(a) : "l"(p));
    return a;
}
#define CP_COMMIT() asm volatile("cp.async.commit_group;" ::: "memory")
#define CP_WAIT(n)  asm volatile("cp.async.wait_group %0;" :: "n"(n) : "memory")

__device__ __forceinline__ void st_h2(__half* p, float a, float b) {
    *(__half2*)p = __float22half2_rn(make_float2(a, b));
}
__device__ __forceinline__ uint32_t pack_h2(float a, float b) {
    __half2 h = __float22half2_rn(make_float2(a, b));
    return *(uint32_t*)&h;
}
__device__ __forceinline__ float ex2(float x) {
    float r;
    asm("ex2.approx.f32 %0, %1;" : "=f"(r) : "f"(x));
    return r;
}
// D(16x8) += A(16x16) * B(16x8), f16 in, f32 accum
__device__ __forceinline__ void mma_f16(float* c, const uint32_t* a,
                                        const uint32_t* b) {
    asm volatile(
        "mma.sync.aligned.m16n8k16.row.col.f32.f16.f16.f32 "
        "{%0,%1,%2,%3}, {%4,%5,%6,%7}, {%8,%9}, {%0,%1,%2,%3};"
        : "+f"(c[0]), "+f"(c[1]), "+f"(c[2]), "+f"(c[3])
        : "r"(a[0]), "r"(a[1]), "r"(a[2]), "r"(a[3]), "r"(b[0]), "r"(b[1]));
}
__device__ __forceinline__ void ldsm_x4(uint32_t& r0, uint32_t& r1,
                                        uint32_t& r2, uint32_t& r3, uint32_t a) {
    asm volatile("ldmatrix.sync.aligned.m8n8.x4.shared.b16 {%0,%1,%2,%3}, [%4];"
                 : "=r"(r0), "=r"(r1), "=r"(r2), "=r"(r3) : "r"(a));
}

// ---------------------------------------------------------------------------
// Fused prologue: y=0..2 build_weff(q/k/v), y=3 build_woeff, y=4 round_x.
// ---------------------------------------------------------------------------
__global__ __launch_bounds__(256) void prep_k(
    const float* __restrict__ x,
    const float* __restrict__ Wq, const float* __restrict__ Wk,
    const float* __restrict__ Wv, const float* __restrict__ Wo,
    const float* __restrict__ aq, const float* __restrict__ ak,
    const float* __restrict__ av, const float* __restrict__ cl)
{
    __shared__ float sS[512];
    const int tid = threadIdx.x;
    const int y = blockIdx.y;

    if (y < 3) {
        const float* W = (y == 0) ? Wq : (y == 1) ? Wk : Wv;
        const float* A = (y == 0) ? aq : (y == 1) ? ak : av;
        sS[tid] = A[tid];
        sS[tid + 256] = A[tid + 256];
        __syncthreads();
        int idx = blockIdx.x * 256 + tid;       // over 64*1024
        int d = idx >> 10, e = idx & 1023;
        float wv[NH];
#pragma unroll
        for (int m = 0; m < NH; m++)
            wv[m] = W[(m * HD + d) * HIDD + e];
        float scale = (y == 0) ? ATTN_SCALE * LOG2E : 1.0f;
#pragma unroll
        for (int hp = 0; hp < 32; hp++) {
            float acc = 0.f;
#pragma unroll
            for (int m = 0; m < NH; m++)
                acc += sS[m * 32 + hp] * wv[m];
            g_Weff[y][hp * HD + d][e] = __float2half_rn(acc * scale);
        }
    } else if (y == 3) {
        sS[tid] = cl[tid];
        sS[tid + 256] = cl[tid + 256];
        __syncthreads();
        int idx = blockIdx.x * 256 + tid;       // over 1024*64
        int f = idx >> 6, d = idx & 63;
        float wv[NH];
#pragma unroll
        for (int h = 0; h < NH; h++)
            wv[h] = Wo[f * HIDD + h * HD + d];
#pragma unroll
        for (int o = 0; o < 32; o++) {
            float acc = 0.f;
#pragma unroll
            for (int h = 0; h < NH; h++)
                acc += sS[h * 32 + o] * wv[h];
            g_Woeff[f][o * HD + d] = __float2half_rn(acc);
        }
    } else {
        const float4* x4 = (const float4*)x;
        uint2* dst = (uint2*)&g_Xr[0][0];
#pragma unroll
        for (int it = 0; it < 8; it++) {
            int idx4 = it * 65536 + blockIdx.x * 256 + tid;
            float4 v = x4[idx4];
            uint2 o;
            o.x = pack_h2(v.x, v.y);
            o.y = pack_h2(v.z, v.w);
            dst[idx4] = o;
        }
    }
}

// zero the f32 output (split-K atomic target)
__global__ __launch_bounds__(256) void zero_k(float4* __restrict__ out)
{
    out[blockIdx.x * 256 + threadIdx.x] = make_float4(0.f, 0.f, 0.f, 0.f);
}

// ---------------------------------------------------------------------------
// smem tiles: rows of 64 halves (128B), XOR chunk swizzle
// ---------------------------------------------------------------------------
#define G_TILEB 16384
#define G_STGB (2 * G_TILEB)
#define NSTG 3
#define SMEM_G (NSTG * G_STGB)           // 96 KB

// ---------------------------------------------------------------------------
// Projection GEMM (fp16): C[2048,2048] = Xr * Weff[z]^T, K=1024.
//   CTA 128x128, 8 warps (4M x 2N), warp 32x64, KC=64, LDSM fragments.
// ---------------------------------------------------------------------------
__global__ __launch_bounds__(256, 2) void gemmA_k()
{
    extern __shared__ __align__(16) char smc[];
    const int tid = threadIdx.x, wid = tid >> 5, lane = tid & 31;
    const int wm = (wid & 3) * 32;
    const int wn = (wid >> 2) * 64;
    const int bn = blockIdx.x * 128, bm = blockIdx.y * 128;
    const int which = blockIdx.z;
    const __half* Aw = &g_Xr[0][0];
    const __half* Bw = &g_Weff[which][0][0];
    const uint32_t sb = smem_u32(smc);
    const int fr = lane >> 2, fc = lane & 3;
    const int lrow = tid >> 1;
    const int cb = (tid & 1) * 4;

    const int li = lane & 7;
    const int g8 = (lane >> 3) & 1, g16 = lane >> 4;
    uint32_t rowOffA[2]; int rmA[2];
#pragma unroll
    for (int mt = 0; mt < 2; mt++) {
        int r = wm + mt * 16 + g8 * 8 + li;
        rowOffA[mt] = (uint32_t)r * 128; rmA[mt] = r & 7;
    }
    uint32_t rowOffB[4]; int rmB[4];
#pragma unroll
    for (int j = 0; j < 4; j++) {
        int r = wn + j * 16 + g16 * 8 + li;
        rowOffB[j] = (uint32_t)r * 128; rmB[j] = r & 7;
    }

    auto issue = [&](int kc) {
        int s = kc % NSTG;
        int k0 = kc * 64;
        uint32_t sa = sb + (uint32_t)s * G_STGB;
        uint32_t sbB = sa + G_TILEB;
        uint32_t dstrow = (uint32_t)lrow * 128;
        int swm = lrow & 7;
        const __half* asrc = Aw + (size_t)(bm + lrow) * HIDD + k0;
        const __half* bsrc = Bw + (size_t)(bn + lrow) * HIDD + k0;
#pragma unroll
        for (int c = 0; c < 4; c++) {
            int cc = cb + c;
            uint32_t off = dstrow + (uint32_t)((cc ^ swm) << 4);
            cp16(sa + off, asrc + cc * 8);
            cp16(sbB + off, bsrc + cc * 8);
        }
    };

    float acc[2][8][4];
#pragma unroll
    for (int mt = 0; mt < 2; mt++)
#pragma unroll
        for (int nt = 0; nt < 8; nt++)
#pragma unroll
            for (int j = 0; j < 4; j++) acc[mt][nt][j] = 0.f;

    issue(0); CP_COMMIT();
    issue(1); CP_COMMIT();

    const int NKC = HIDD / 64;
    for (int kc = 0; kc < NKC; kc++) {
        CP_WAIT(1);
        __syncthreads();
        if (kc + 2 < NKC) issue(kc + 2);
        CP_COMMIT();
        uint32_t Ab = sb + (uint32_t)(kc % NSTG) * G_STGB;
        uint32_t Bb = Ab + G_TILEB;
#pragma unroll
        for (int k16 = 0; k16 < 4; k16++) {
            uint32_t afr[2][4], bfr[8][2];
#pragma unroll
            for (int mt = 0; mt < 2; mt++) {
                uint32_t a = Ab + rowOffA[mt] +
                    (uint32_t)((((2 * k16) + g16) ^ rmA[mt]) << 4);
                ldsm_x4(afr[mt][0], afr[mt][1], afr[mt][2], afr[mt][3], a);
            }
#pragma unroll
            for (int j = 0; j < 4; j++) {
                uint32_t a = Bb + rowOffB[j] +
                    (uint32_t)((((2 * k16) + g8) ^ rmB[j]) << 4);
                ldsm_x4(bfr[2 * j][0], bfr[2 * j][1],
                        bfr[2 * j + 1][0], bfr[2 * j + 1][1], a);
            }
#pragma unroll
            for (int mt = 0; mt < 2; mt++)
#pragma unroll
                for (int nt = 0; nt < 8; nt++)
                    mma_f16(acc[mt][nt], afr[mt], bfr[nt]);
        }
    }

    // ---- epilogue (natural layouts) ----
    if (which == 2) {
        int h = bn >> 7, p = (wn >> 6) & 1;
#pragma unroll
        for (int mt = 0; mt < 2; mt++) {
#pragma unroll
            for (int half_ = 0; half_ < 2; half_++) {
                int row = bm + wm + mt * 16 + fr + half_ * 8;
                int b = row >> 10, n = row & 1023;
                int kv = n * NP + p;
                __half* Vt = &g_Vt[b * NH + h][0][0];
#pragma unroll
                for (int nt = 0; nt < 8; nt++) {
                    int d = nt * 8 + 2 * fc;
                    Vt[(size_t)d * SVLEN + kv] =
                        __float2half_rn(acc[mt][nt][half_ * 2 + 0]);
                    Vt[(size_t)(d + 1) * SVLEN + kv] =
                        __float2half_rn(acc[mt][nt][half_ * 2 + 1]);
                }
            }
        }
    } else {
        __half* dst0 = (which == 0) ? &g_Q[0][0][0] : &g_K[0][0][0];
#pragma unroll
        for (int mt = 0; mt < 2; mt++) {
#pragma unroll
            for (int half_ = 0; half_ < 2; half_++) {
                int row = bm + wm + mt * 16 + fr + half_ * 8;
                int b = row >> 10, n = row & 1023;
#pragma unroll
                for (int nt = 0; nt < 8; nt++) {
                    int col = bn + wn + nt * 8 + 2 * fc;
                    int h = col >> 7, p = (col >> 6) & 1, d = col & 63;
                    __half* dst = dst0 +
                        ((size_t)(b * NH + h) * SVLEN + n * NP + p) * HD + d;
                    st_h2(dst, acc[mt][nt][half_ * 2 + 0],
                               acc[mt][nt][half_ * 2 + 1]);
                }
            }
        }
    }
}

// ---------------------------------------------------------------------------
// Output GEMM (fp16), split-K=2: out[2048,1024] += gather(g_Aout)*Woeff^T
//   over K half [z*1024, z*1024+1024). CTA 128x128, warp 32x64 (gemmA's
//   proven layout), KC=64, NSTG=3. Epilogue: atomicAdd f32 (pre-zeroed out;
//   exactly 2 contributors -> commutative -> deterministic).
// ---------------------------------------------------------------------------
__global__ __launch_bounds__(256, 2) void gemmO_k(float* __restrict__ Cout)
{
    extern __shared__ __align__(16) char smc[];
    const int tid = threadIdx.x, wid = tid >> 5, lane = tid & 31;
    const int wm = (wid & 3) * 32;
    const int wn = (wid >> 2) * 64;
    const int bn = blockIdx.x * 128, bm = blockIdx.y * 128;
    const int kbase = blockIdx.z * (NPROJ / 2);      // 0 or 1024
    const __half* Bw = &g_Woeff[0][0];
    const uint32_t sb = smem_u32(smc);
    const int fr = lane >> 2, fc = lane & 3;
    const int lrow = tid >> 1;
    const int cb = (tid & 1) * 4;

    const int li = lane & 7;
    const int g8 = (lane >> 3) & 1, g16 = lane >> 4;
    uint32_t rowOffA[2]; int rmA[2];
#pragma unroll
    for (int mt = 0; mt < 2; mt++) {
        int r = wm + mt * 16 + g8 * 8 + li;
        rowOffA[mt] = (uint32_t)r * 128; rmA[mt] = r & 7;
    }
    uint32_t rowOffB[4]; int rmB[4];
#pragma unroll
    for (int j = 0; j < 4; j++) {
        int r = wn + j * 16 + g16 * 8 + li;
        rowOffB[j] = (uint32_t)r * 128; rmB[j] = r & 7;
    }

    int t = bm + lrow;
    int gb = t >> 10, gn = t & 1023;

    auto issue = [&](int kc) {
        int s = kc % NSTG;
        int k0 = kbase + kc * 64;
        uint32_t sa = sb + (uint32_t)s * G_STGB;
        uint32_t sbB = sa + G_TILEB;
        uint32_t dstrow = (uint32_t)lrow * 128;
        int swm = lrow & 7;
#pragma unroll
        for (int c = 0; c < 4; c++) {
            int cc = cb + c;
            uint32_t off = dstrow + (uint32_t)((cc ^ swm) << 4);
            int col = k0 + cc * 8;
            int o = col >> 6, dd = col & 63;
            cp16(sa + off,
                 &g_Aout[gb * NH + (o >> 1)][gn * NP + (o & 1)][dd]);
        }
        const __half* bsrc = Bw + (size_t)(bn + lrow) * NPROJ + k0;
#pragma unroll
        for (int c = 0; c < 4; c++) {
            int cc = cb + c;
            uint32_t off = dstrow + (uint32_t)((cc ^ swm) << 4);
            cp16(sbB + off, bsrc + cc * 8);
        }
    };

    float acc[2][8][4];
#pragma unroll
    for (int mt = 0; mt < 2; mt++)
#pragma unroll
        for (int nt = 0; nt < 8; nt++)
#pragma unroll
            for (int j = 0; j < 4; j++) acc[mt][nt][j] = 0.f;

    issue(0); CP_COMMIT();
    issue(1); CP_COMMIT();

    const int NKC = (NPROJ / 2) / 64;   // 16
    for (int kc = 0; kc < NKC; kc++) {
        CP_WAIT(1);
        __syncthreads();
        if (kc + 2 < NKC) issue(kc + 2);
        CP_COMMIT();
        uint32_t Ab = sb + (uint32_t)(kc % NSTG) * G_STGB;
        uint32_t Bb = Ab + G_TILEB;
#pragma unroll
        for (int k16 = 0; k16 < 4; k16++) {
            uint32_t afr[2][4], bfr[8][2];
#pragma unroll
            for (int mt = 0; mt < 2; mt++) {
                uint32_t a = Ab + rowOffA[mt] +
                    (uint32_t)((((2 * k16) + g16) ^ rmA[mt]) << 4);
                ldsm_x4(afr[mt][0], afr[mt][1], afr[mt][2], afr[mt][3], a);
            }
#pragma unroll
            for (int j = 0; j < 4; j++) {
                uint32_t a = Bb + rowOffB[j] +
                    (uint32_t)((((2 * k16) + g8) ^ rmB[j]) << 4);
                ldsm_x4(bfr[2 * j][0], bfr[2 * j][1],
                        bfr[2 * j + 1][0], bfr[2 * j + 1][1], a);
            }
#pragma unroll
            for (int mt = 0; mt < 2; mt++)
#pragma unroll
                for (int nt = 0; nt < 8; nt++)
                    mma_f16(acc[mt][nt], afr[mt], bfr[nt]);
        }
    }

    // split-K epilogue: accumulate into pre-zeroed f32 output
#pragma unroll
    for (int mt = 0; mt < 2; mt++) {
#pragma unroll
        for (int half_ = 0; half_ < 2; half_++) {
            int row = bm + wm + mt * 16 + fr + half_ * 8;
            float* dst = Cout + (size_t)row * HIDD;
#pragma unroll
            for (int nt = 0; nt < 8; nt++) {
                int col = bn + wn + nt * 8 + 2 * fc;
                atomicAdd(dst + col,     acc[mt][nt][half_ * 2 + 0]);
                atomicAdd(dst + col + 1, acc[mt][nt][half_ * 2 + 1]);
            }
        }
    }
}

// ---------------------------------------------------------------------------
// Causal flash attention (round-13 form): fp16 MMA + LDSM, log2 softmax,
//   q-tile 128 (warp 16 rows), k-tile 64, 4-buffer KV ring (depth 3),
//   Q fragments preloaded, P in registers.
// ---------------------------------------------------------------------------
#define Q_B 16384
#define KV_B 8192
#define ATTN_NBUF 4
#define SMEM_ATTN (Q_B + ATTN_NBUF * 2 * KV_B)   // 81,920 B

__global__ __launch_bounds__(256, 2) void attn_k()
{
    extern __shared__ __align__(16) char smc[];
    const uint32_t sQ = smem_u32(smc);
    const uint32_t sKV = sQ + Q_B;

    const int bh = blockIdx.y;
    const int qt = (gridDim.x - 1) - blockIdx.x;   // heavy tiles first
    const int qstart = qt * 128;
    const __half* Qg = &g_Q[bh][0][0];
    const __half* Kg = &g_K[bh][0][0];
    const __half* Vtg = &g_Vt[bh][0][0];

    const int tid = threadIdx.x;
    const int wq = tid >> 5;
    const int lane = tid & 31;
    const int fr = lane >> 2;
    const int fc = lane & 3;
    const int r0 = wq * 16 + fr, r1 = r0 + 8;

    const int li = lane & 7;
    const int g8 = (lane >> 3) & 1, g16 = lane >> 4;
    const int rowQ = wq * 16 + g8 * 8 + li;
    const uint32_t rowOffQ = (uint32_t)rowQ * 128;
    const int rmQ = rowQ & 7;
    uint32_t rowOffKV[4]; int rmKV[4];
#pragma unroll
    for (int j = 0; j < 4; j++) {
        int r = j * 16 + g16 * 8 + li;
        rowOffKV[j] = (uint32_t)r * 128; rmKV[j] = r & 7;
    }

    auto issue_kv = [&](int jt) {
        int buf = jt % ATTN_NBUF;
        uint32_t sK = sKV + (uint32_t)buf * (2 * KV_B);
        uint32_t sV = sK + KV_B;
        int kstart = jt * 64;
#pragma unroll
        for (int it = 0; it < 2; it++) {
            int chunk = tid + 256 * it;
            int row = chunk >> 3;
            int cc = chunk & 7;
            uint32_t off = (uint32_t)row * 128 +
                           (uint32_t)((cc ^ (row & 7)) << 4);
            cp16(sK + off, Kg + (size_t)(kstart + row) * HD + cc * 8);
            cp16(sV + off, Vtg + (size_t)row * SVLEN + kstart + cc * 8);
        }
    };

    // prologue: (Q + kv0) group, kv1 group, kv2 group
#pragma unroll
    for (int it = 0; it < 4; it++) {
        int chunk = tid + 256 * it;
        int row = chunk >> 3;
        int cc = chunk & 7;
        uint32_t off = (uint32_t)row * 128 + (uint32_t)((cc ^ (row & 7)) << 4);
        cp16(sQ + off, Qg + (size_t)(qstart + row) * HD + cc * 8);
    }
    issue_kv(0); CP_COMMIT();
    issue_kv(1); CP_COMMIT();
    issue_kv(2); CP_COMMIT();      // may overrun jmax; in-bounds (sv=2048)

    float O[8][4];
    float m0 = NEG_INF, m1 = NEG_INF, l0 = 0.f, l1 = 0.f;
#pragma unroll
    for (int nt = 0; nt < 8; nt++)
#pragma unroll
        for (int j = 0; j < 4; j++) O[nt][j] = 0.f;

    uint32_t qfr[4][4];

    const int jmax = 2 * qt + 1;
    for (int jt = 0; jt <= jmax; jt++) {
        const int kstart = jt * 64;
        CP_WAIT(2);           // tile jt (and Q at jt=0) complete
        __syncthreads();      // all warps finished with buf (jt-1)
        if (jt + 3 <= jmax) issue_kv(jt + 3);
        CP_COMMIT();
        uint32_t Kb = sKV + (uint32_t)(jt % ATTN_NBUF) * (2 * KV_B);
        uint32_t Vb = Kb + KV_B;

        if (jt == 0) {
#pragma unroll
            for (int k16 = 0; k16 < 4; k16++) {
                uint32_t a = sQ + rowOffQ +
                    (uint32_t)((((2 * k16) + g16) ^ rmQ) << 4);
                ldsm_x4(qfr[k16][0], qfr[k16][1], qfr[k16][2], qfr[k16][3], a);
            }
        }

        // ---- S = Q K^T (pre-scaled by scale*log2e) ----
        float s[8][4];
#pragma unroll
        for (int nt = 0; nt < 8; nt++)
#pragma unroll
            for (int j = 0; j < 4; j++) s[nt][j] = 0.f;
#pragma unroll
        for (int k16 = 0; k16 < 4; k16++) {
            uint32_t bfr[8][2];
#pragma unroll
            for (int j = 0; j < 4; j++) {
                uint32_t a = Kb + rowOffKV[j] +
                    (uint32_t)((((2 * k16) + g8) ^ rmKV[j]) << 4);
                ldsm_x4(bfr[2 * j][0], bfr[2 * j][1],
                        bfr[2 * j + 1][0], bfr[2 * j + 1][1], a);
            }
#pragma unroll
            for (int nt = 0; nt < 8; nt++)
                mma_f16(s[nt], qfr[k16], bfr[nt]);
        }

        // causal mask
        if (kstart + 63 > qstart + wq * 16) {
            int gr0 = qstart + r0, gr1 = gr0 + 8;
#pragma unroll
            for (int nt = 0; nt < 8; nt++) {
                int c0 = kstart + nt * 8 + 2 * fc;
                if (c0 > gr0)     s[nt][0] = NEG_INF;
                if (c0 + 1 > gr0) s[nt][1] = NEG_INF;
                if (c0 > gr1)     s[nt][2] = NEG_INF;
                if (c0 + 1 > gr1) s[nt][3] = NEG_INF;
            }
        }

        // ---- online softmax in log2 domain ----
        float mx0 = NEG_INF, mx1 = NEG_INF;
#pragma unroll
        for (int nt = 0; nt < 8; nt++) {
            mx0 = fmaxf(mx0, fmaxf(s[nt][0], s[nt][1]));
            mx1 = fmaxf(mx1, fmaxf(s[nt][2], s[nt][3]));
        }
        mx0 = fmaxf(mx0, __shfl_xor_sync(0xffffffffu, mx0, 1));
        mx0 = fmaxf(mx0, __shfl_xor_sync(0xffffffffu, mx0, 2));
        mx1 = fmaxf(mx1, __shfl_xor_sync(0xffffffffu, mx1, 1));
        mx1 = fmaxf(mx1, __shfl_xor_sync(0xffffffffu, mx1, 2));
        float newm0 = fmaxf(m0, mx0), newm1 = fmaxf(m1, mx1);
        float al0 = ex2(m0 - newm0), al1 = ex2(m1 - newm1);

        uint32_t pfr[4][4];
        float rs0 = 0.f, rs1 = 0.f;
#pragma unroll
        for (int nt = 0; nt < 8; nt++) {
            float p0 = ex2(s[nt][0] - newm0);
            float p1 = ex2(s[nt][1] - newm0);
            float p2 = ex2(s[nt][2] - newm1);
            float p3 = ex2(s[nt][3] - newm1);
            rs0 += p0 + p1; rs1 += p2 + p3;
            int t16 = nt >> 1, hi = nt & 1;
            pfr[t16][hi * 2 + 0] = pack_h2(p0, p1);   // row r0
            pfr[t16][hi * 2 + 1] = pack_h2(p2, p3);   // row r1
        }
        rs0 += __shfl_xor_sync(0xffffffffu, rs0, 1);
        rs0 += __shfl_xor_sync(0xffffffffu, rs0, 2);
        rs1 += __shfl_xor_sync(0xffffffffu, rs1, 1);
        rs1 += __shfl_xor_sync(0xffffffffu, rs1, 2);
        l0 = l0 * al0 + rs0; l1 = l1 * al1 + rs1;
        m0 = newm0; m1 = newm1;
#pragma unroll
        for (int nt = 0; nt < 8; nt++) {
            O[nt][0] *= al0; O[nt][1] *= al0;
            O[nt][2] *= al1; O[nt][3] *= al1;
        }

        // ---- O += P V (A in regs; B via LDSM from Vts[d][kv]) ----
#pragma unroll
        for (int k16 = 0; k16 < 4; k16++) {
            uint32_t bfr[8][2];
#pragma unroll
            for (int j = 0; j < 4; j++) {
                uint32_t a = Vb + rowOffKV[j] +
                    (uint32_t)((((2 * k16) + g8) ^ rmKV[j]) << 4);
                ldsm_x4(bfr[2 * j][0], bfr[2 * j][1],
                        bfr[2 * j + 1][0], bfr[2 * j + 1][1], a);
            }
#pragma unroll
            for (int nt = 0; nt < 8; nt++)
                mma_f16(O[nt], pfr[k16], bfr[nt]);
        }
    }

    // epilogue: normalize, store natural fp16 into g_Aout
    __half* Ag = &g_Aout[bh][0][0];
    float inv0 = 1.f / l0, inv1 = 1.f / l1;
#pragma unroll
    for (int nt = 0; nt < 8; nt++) {
        int pos = nt * 8 + 2 * fc;
        st_h2(Ag + (size_t)(qstart + r0) * HD + pos,
              O[nt][0] * inv0, O[nt][1] * inv0);
        st_h2(Ag + (size_t)(qstart + r1) * HD + pos,
              O[nt][2] * inv1, O[nt][3] * inv1);
    }
}

// ---------------------------------------------------------------------------
// launch
// ---------------------------------------------------------------------------
extern "C" void kernel_launch(void* const* d_in, const int* in_sizes, int n_in,
                              void* d_out, int out_size)
{
    const float* x  = (const float*)d_in[0];
    const float* Wq = (const float*)d_in[1];
    const float* Wk = (const float*)d_in[2];
    const float* Wv = (const float*)d_in[3];
    const float* Wo = (const float*)d_in[4];
    const float* aq = (const float*)d_in[5];
    const float* ak = (const float*)d_in[6];
    const float* av = (const float*)d_in[7];
    const float* cl = (const float*)d_in[8];
    float* out = (float*)d_out;

    cudaFuncSetAttribute(gemmA_k, cudaFuncAttributeMaxDynamicSharedMemorySize, SMEM_G);
    cudaFuncSetAttribute(gemmO_k, cudaFuncAttributeMaxDynamicSharedMemorySize, SMEM_G);
    cudaFuncSetAttribute(attn_k, cudaFuncAttributeMaxDynamicSharedMemorySize, SMEM_ATTN);

    // fused prologue + output zeroing (zero feeds gemmO's atomic epilogue)
    prep_k<<<dim3(256, 5), 256>>>(x, Wq, Wk, Wv, Wo, aq, ak, av, cl);
    zero_k<<<(MTOK * HIDD / 4) / 256, 256>>>((float4*)out);

    // projections + head mixing (q/k/v via z)
    gemmA_k<<<dim3(NPROJ / 128, MTOK / 128, 3), 256, SMEM_G>>>();

    // causal SDPA over virtual positions
    attn_k<<<dim3(SVLEN / 128, NB * NH), 256, SMEM_ATTN>>>();

    // collapse + output projection: split-K=2, 256 CTAs, gemmA-grade tiles
    gemmO_k<<<dim3(HIDD / 128, MTOK / 128, 2), 256, SMEM_G>>>(out);
}

// round 17
// speedup vs baseline: 1.0446x; 1.0391x over previous
#include <cuda_runtime.h>
#include <cuda_fp16.h>
#include <cstdint>

// ---------------------------------------------------------------------------
// InterleavedHeadAttention — round 16
//   - attention softmax slimmed: f16x2 exp (ex2.approx.f16x2 writes the PV
//     A-fragment directly), rowsum via ones-MMA, warp-uniform rescale skip
//   - gemmO reverted to round-13 form (split-K falsified)
//   B=2, S=1024, HID=1024, H=16, P=2, D=64, sv=2048
// ---------------------------------------------------------------------------

#define NB 2
#define SEQ 1024
#define HIDD 1024
#define NH 16
#define NP 2
#define HD 64
#define SVLEN (SEQ * NP)        // 2048
#define MTOK (NB * SEQ)         // 2048
#define NPROJ (NH * NP * HD)    // 2048
#define ATTN_SCALE 0.125f
#define LOG2E 1.4426950408889634f

#define NEG_INF __int_as_float(0xff800000)

// fp16 storage, all natural layouts
__device__ __half g_Weff[3][NPROJ][HIDD];
__device__ __half g_Woeff[HIDD][NPROJ];      // [f][o*64+d]
__device__ __half g_Xr[MTOK][HIDD];
__device__ __half g_Q[NB * NH][SVLEN][HD];
__device__ __half g_K[NB * NH][SVLEN][HD];
__device__ __half g_Vt[NB * NH][HD][SVLEN];  // transposed
__device__ __half g_Aout[NB * NH][SVLEN][HD];

// ---------------------------------------------------------------------------
// helpers
// ---------------------------------------------------------------------------
__device__ __forceinline__ void cp16(uint32_t s, const void* g) {
    asm volatile("cp.async.cg.shared.global [%0], [%1], 16;" :: "r"(s), "l"(g));
}
__device__ __forceinline__ uint32_t smem_u32(const void* p) {
    uint32_t a;
    asm("{ .reg .u64 t; cvta.to.shared.u64 t, %1; cvt.u32.u64 %0, t; }"
        : "=r"(a) : "l"(p));
    return a;
}
#define CP_COMMIT() asm volatile("cp.async.commit_group;" ::: "memory")
#define CP_WAIT(n)  asm volatile("cp.async.wait_group %0;" :: "n"(n) : "memory")

__device__ __forceinline__ void st_h2(__half* p, float a, float b) {
    *(__half2*)p = __float22half2_rn(make_float2(a, b));
}
__device__ __forceinline__ uint32_t pack_h2(float a, float b) {
    __half2 h = __float22half2_rn(make_float2(a, b));
    return *(uint32_t*)&h;
}
__device__ __forceinline__ float ex2(float x) {
    float r;
    asm("ex2.approx.f32 %0, %1;" : "=f"(r) : "f"(x));
    return r;
}
// pack two f32 into f16x2: lo = lo-arg, hi = hi-arg
__device__ __forceinline__ uint32_t cvt2h(float hi, float lo) {
    uint32_t r;
    asm("cvt.rn.f16x2.f32 %0, %1, %2;" : "=r"(r) : "f"(hi), "f"(lo));
    return r;
}
__device__ __forceinline__ uint32_t ex2h2(uint32_t a) {
    uint32_t r;
    asm("ex2.approx.f16x2 %0, %1;" : "=r"(r) : "r"(a));
    return r;
}
// D(16x8) += A(16x16) * B(16x8), f16 in, f32 accum
__device__ __forceinline__ void mma_f16(float* c, const uint32_t* a,
                                        const uint32_t* b) {
    asm volatile(
        "mma.sync.aligned.m16n8k16.row.col.f32.f16.f16.f32 "
        "{%0,%1,%2,%3}, {%4,%5,%6,%7}, {%8,%9}, {%0,%1,%2,%3};"
        : "+f"(c[0]), "+f"(c[1]), "+f"(c[2]), "+f"(c[3])
        : "r"(a[0]), "r"(a[1]), "r"(a[2]), "r"(a[3]), "r"(b[0]), "r"(b[1]));
}
__device__ __forceinline__ void ldsm_x4(uint32_t& r0, uint32_t& r1,
                                        uint32_t& r2, uint32_t& r3, uint32_t a) {
    asm volatile("ldmatrix.sync.aligned.m8n8.x4.shared.b16 {%0,%1,%2,%3}, [%4];"
                 : "=r"(r0), "=r"(r1), "=r"(r2), "=r"(r3) : "r"(a));
}

// ---------------------------------------------------------------------------
// Fused prologue: y=0..2 build_weff(q/k/v), y=3 build_woeff, y=4 round_x.
// ---------------------------------------------------------------------------
__global__ __launch_bounds__(256) void prep_k(
    const float* __restrict__ x,
    const float* __restrict__ Wq, const float* __restrict__ Wk,
    const float* __restrict__ Wv, const float* __restrict__ Wo,
    const float* __restrict__ aq, const float* __restrict__ ak,
    const float* __restrict__ av, const float* __restrict__ cl)
{
    __shared__ float sS[512];
    const int tid = threadIdx.x;
    const int y = blockIdx.y;

    if (y < 3) {
        const float* W = (y == 0) ? Wq : (y == 1) ? Wk : Wv;
        const float* A = (y == 0) ? aq : (y == 1) ? ak : av;
        sS[tid] = A[tid];
        sS[tid + 256] = A[tid + 256];
        __syncthreads();
        int idx = blockIdx.x * 256 + tid;       // over 64*1024
        int d = idx >> 10, e = idx & 1023;
        float wv[NH];
#pragma unroll
        for (int m = 0; m < NH; m++)
            wv[m] = W[(m * HD + d) * HIDD + e];
        float scale = (y == 0) ? ATTN_SCALE * LOG2E : 1.0f;
#pragma unroll
        for (int hp = 0; hp < 32; hp++) {
            float acc = 0.f;
#pragma unroll
            for (int m = 0; m < NH; m++)
                acc += sS[m * 32 + hp] * wv[m];
            g_Weff[y][hp * HD + d][e] = __float2half_rn(acc * scale);
        }
    } else if (y == 3) {
        sS[tid] = cl[tid];
        sS[tid + 256] = cl[tid + 256];
        __syncthreads();
        int idx = blockIdx.x * 256 + tid;       // over 1024*64
        int f = idx >> 6, d = idx & 63;
        float wv[NH];
#pragma unroll
        for (int h = 0; h < NH; h++)
            wv[h] = Wo[f * HIDD + h * HD + d];
#pragma unroll
        for (int o = 0; o < 32; o++) {
            float acc = 0.f;
#pragma unroll
            for (int h = 0; h < NH; h++)
                acc += sS[h * 32 + o] * wv[h];
            g_Woeff[f][o * HD + d] = __float2half_rn(acc);
        }
    } else {
        const float4* x4 = (const float4*)x;
        uint2* dst = (uint2*)&g_Xr[0][0];
#pragma unroll
        for (int it = 0; it < 8; it++) {
            int idx4 = it * 65536 + blockIdx.x * 256 + tid;
            float4 v = x4[idx4];
            uint2 o;
            o.x = pack_h2(v.x, v.y);
            o.y = pack_h2(v.z, v.w);
            dst[idx4] = o;
        }
    }
}

// ---------------------------------------------------------------------------
// gemmA smem tiles: rows of 64 halves (128B), XOR chunk swizzle
// ---------------------------------------------------------------------------
#define G_TILEB 16384
#define G_STGB (2 * G_TILEB)
#define NSTG 3
#define SMEM_G (NSTG * G_STGB)           // 96 KB

// ---------------------------------------------------------------------------
// Projection GEMM (fp16): C[2048,2048] = Xr * Weff[z]^T, K=1024.
// ---------------------------------------------------------------------------
__global__ __launch_bounds__(256, 2) void gemmA_k()
{
    extern __shared__ __align__(16) char smc[];
    const int tid = threadIdx.x, wid = tid >> 5, lane = tid & 31;
    const int wm = (wid & 3) * 32;
    const int wn = (wid >> 2) * 64;
    const int bn = blockIdx.x * 128, bm = blockIdx.y * 128;
    const int which = blockIdx.z;
    const __half* Aw = &g_Xr[0][0];
    const __half* Bw = &g_Weff[which][0][0];
    const uint32_t sb = smem_u32(smc);
    const int fr = lane >> 2, fc = lane & 3;
    const int lrow = tid >> 1;
    const int cb = (tid & 1) * 4;

    const int li = lane & 7;
    const int g8 = (lane >> 3) & 1, g16 = lane >> 4;
    uint32_t rowOffA[2]; int rmA[2];
#pragma unroll
    for (int mt = 0; mt < 2; mt++) {
        int r = wm + mt * 16 + g8 * 8 + li;
        rowOffA[mt] = (uint32_t)r * 128; rmA[mt] = r & 7;
    }
    uint32_t rowOffB[4]; int rmB[4];
#pragma unroll
    for (int j = 0; j < 4; j++) {
        int r = wn + j * 16 + g16 * 8 + li;
        rowOffB[j] = (uint32_t)r * 128; rmB[j] = r & 7;
    }

    auto issue = [&](int kc) {
        int s = kc % NSTG;
        int k0 = kc * 64;
        uint32_t sa = sb + (uint32_t)s * G_STGB;
        uint32_t sbB = sa + G_TILEB;
        uint32_t dstrow = (uint32_t)lrow * 128;
        int swm = lrow & 7;
        const __half* asrc = Aw + (size_t)(bm + lrow) * HIDD + k0;
        const __half* bsrc = Bw + (size_t)(bn + lrow) * HIDD + k0;
#pragma unroll
        for (int c = 0; c < 4; c++) {
            int cc = cb + c;
            uint32_t off = dstrow + (uint32_t)((cc ^ swm) << 4);
            cp16(sa + off, asrc + cc * 8);
            cp16(sbB + off, bsrc + cc * 8);
        }
    };

    float acc[2][8][4];
#pragma unroll
    for (int mt = 0; mt < 2; mt++)
#pragma unroll
        for (int nt = 0; nt < 8; nt++)
#pragma unroll
            for (int j = 0; j < 4; j++) acc[mt][nt][j] = 0.f;

    issue(0); CP_COMMIT();
    issue(1); CP_COMMIT();

    const int NKC = HIDD / 64;
    for (int kc = 0; kc < NKC; kc++) {
        CP_WAIT(1);
        __syncthreads();
        if (kc + 2 < NKC) issue(kc + 2);
        CP_COMMIT();
        uint32_t Ab = sb + (uint32_t)(kc % NSTG) * G_STGB;
        uint32_t Bb = Ab + G_TILEB;
#pragma unroll
        for (int k16 = 0; k16 < 4; k16++) {
            uint32_t afr[2][4], bfr[8][2];
#pragma unroll
            for (int mt = 0; mt < 2; mt++) {
                uint32_t a = Ab + rowOffA[mt] +
                    (uint32_t)((((2 * k16) + g16) ^ rmA[mt]) << 4);
                ldsm_x4(afr[mt][0], afr[mt][1], afr[mt][2], afr[mt][3], a);
            }
#pragma unroll
            for (int j = 0; j < 4; j++) {
                uint32_t a = Bb + rowOffB[j] +
                    (uint32_t)((((2 * k16) + g8) ^ rmB[j]) << 4);
                ldsm_x4(bfr[2 * j][0], bfr[2 * j][1],
                        bfr[2 * j + 1][0], bfr[2 * j + 1][1], a);
            }
#pragma unroll
            for (int mt = 0; mt < 2; mt++)
#pragma unroll
                for (int nt = 0; nt < 8; nt++)
                    mma_f16(acc[mt][nt], afr[mt], bfr[nt]);
        }
    }

    // ---- epilogue (natural layouts) ----
    if (which == 2) {
        int h = bn >> 7, p = (wn >> 6) & 1;
#pragma unroll
        for (int mt = 0; mt < 2; mt++) {
#pragma unroll
            for (int half_ = 0; half_ < 2; half_++) {
                int row = bm + wm + mt * 16 + fr + half_ * 8;
                int b = row >> 10, n = row & 1023;
                int kv = n * NP + p;
                __half* Vt = &g_Vt[b * NH + h][0][0];
#pragma unroll
                for (int nt = 0; nt < 8; nt++) {
                    int d = nt * 8 + 2 * fc;
                    Vt[(size_t)d * SVLEN + kv] =
                        __float2half_rn(acc[mt][nt][half_ * 2 + 0]);
                    Vt[(size_t)(d + 1) * SVLEN + kv] =
                        __float2half_rn(acc[mt][nt][half_ * 2 + 1]);
                }
            }
        }
    } else {
        __half* dst0 = (which == 0) ? &g_Q[0][0][0] : &g_K[0][0][0];
#pragma unroll
        for (int mt = 0; mt < 2; mt++) {
#pragma unroll
            for (int half_ = 0; half_ < 2; half_++) {
                int row = bm + wm + mt * 16 + fr + half_ * 8;
                int b = row >> 10, n = row & 1023;
#pragma unroll
                for (int nt = 0; nt < 8; nt++) {
                    int col = bn + wn + nt * 8 + 2 * fc;
                    int h = col >> 7, p = (col >> 6) & 1, d = col & 63;
                    __half* dst = dst0 +
                        ((size_t)(b * NH + h) * SVLEN + n * NP + p) * HD + d;
                    st_h2(dst, acc[mt][nt][half_ * 2 + 0],
                               acc[mt][nt][half_ * 2 + 1]);
                }
            }
        }
    }
}

// ---------------------------------------------------------------------------
// Output GEMM (fp16): out[2048,1024] = gather(g_Aout) * Woeff^T, K=2048.
//   CTA 64x128, KC=128 (16 chunks), NSTG=2 depth-1 prefetch, 256 CTAs.
// ---------------------------------------------------------------------------
#define O_AB 16384                       // A tile: 64 rows x 256B
#define O_BB 32768                       // B tile: 128 rows x 256B
#define O_STGB (O_AB + O_BB)             // 48 KB / stage
#define SMEM_O (2 * O_STGB)              // 96 KB

__global__ __launch_bounds__(256, 2) void gemmO_k(float* __restrict__ Cout)
{
    extern __shared__ __align__(16) char smc[];
    const int tid = threadIdx.x, wid = tid >> 5, lane = tid & 31;
    const int wm = (wid & 1) * 32;
    const int wn = (wid >> 1) * 32;
    const int bn = blockIdx.x * 128, bm = blockIdx.y * 64;
    const __half* Bw = &g_Woeff[0][0];
    const uint32_t sb = smem_u32(smc);
    const int fr = lane >> 2, fc = lane & 3;

    const int li = lane & 7;
    const int g8 = (lane >> 3) & 1, g16 = lane >> 4;
    uint32_t rowOffA[2]; int rmA[2];
#pragma unroll
    for (int mt = 0; mt < 2; mt++) {
        int r = wm + mt * 16 + g8 * 8 + li;
        rowOffA[mt] = (uint32_t)r * 256; rmA[mt] = r & 7;
    }
    uint32_t rowOffB[2]; int rmB[2];
#pragma unroll
    for (int j = 0; j < 2; j++) {
        int r = wn + j * 16 + g16 * 8 + li;
        rowOffB[j] = (uint32_t)r * 256; rmB[j] = r & 7;
    }

    const int arow = tid >> 2;
    const int ab2 = (tid & 3) * 2;
    const int brow = tid >> 1;
    const int bb4 = (tid & 1) * 4;

    int ta = bm + arow;
    int gb = ta >> 10, gn = ta & 1023;

    auto issue = [&](int kc) {
        int s = kc & 1;
        int k0 = kc * 128;
        uint32_t sa = sb + (uint32_t)s * O_STGB;
        uint32_t sbB = sa + O_AB;
        {
            uint32_t dstrow = (uint32_t)arow * 256;
            int swm = arow & 7;
#pragma unroll
            for (int c = 0; c < 4; c++) {
                int cc = ab2 + (c & 1) + (c >> 1) * 8;
                uint32_t off = dstrow + (uint32_t)((cc ^ swm) << 4);
                int col = k0 + cc * 8;
                int o = col >> 6, dd = col & 63;
                cp16(sa + off,
                     &g_Aout[gb * NH + (o >> 1)][gn * NP + (o & 1)][dd]);
            }
        }
        {
            uint32_t dstrow = (uint32_t)brow * 256;
            int swm = brow & 7;
            const __half* bsrc = Bw + (size_t)(bn + brow) * NPROJ + k0;
#pragma unroll
            for (int c = 0; c < 8; c++) {
                int cc = bb4 + (c & 3) + (c >> 2) * 8;
                uint32_t off = dstrow + (uint32_t)((cc ^ swm) << 4);
                cp16(sbB + off, bsrc + cc * 8);
            }
        }
    };

    float acc[2][4][4];
#pragma unroll
    for (int mt = 0; mt < 2; mt++)
#pragma unroll
        for (int nt = 0; nt < 4; nt++)
#pragma unroll
            for (int j = 0; j < 4; j++) acc[mt][nt][j] = 0.f;

    issue(0); CP_COMMIT();

    const int NKC = NPROJ / 128;   // 16
    for (int kc = 0; kc < NKC; kc++) {
        CP_WAIT(0);
        __syncthreads();
        if (kc + 1 < NKC) issue(kc + 1);
        CP_COMMIT();
        uint32_t Ab = sb + (uint32_t)(kc & 1) * O_STGB;
        uint32_t Bb = Ab + O_AB;
#pragma unroll
        for (int k16 = 0; k16 < 8; k16++) {
            uint32_t afr[2][4], bfr[4][2];
#pragma unroll
            for (int mt = 0; mt < 2; mt++) {
                uint32_t a = Ab + rowOffA[mt] +
                    (uint32_t)((((2 * k16) + g16) ^ rmA[mt]) << 4);
                ldsm_x4(afr[mt][0], afr[mt][1], afr[mt][2], afr[mt][3], a);
            }
#pragma unroll
            for (int j = 0; j < 2; j++) {
                uint32_t a = Bb + rowOffB[j] +
                    (uint32_t)((((2 * k16) + g8) ^ rmB[j]) << 4);
                ldsm_x4(bfr[2 * j][0], bfr[2 * j][1],
                        bfr[2 * j + 1][0], bfr[2 * j + 1][1], a);
            }
#pragma unroll
            for (int mt = 0; mt < 2; mt++)
#pragma unroll
                for (int nt = 0; nt < 4; nt++)
                    mma_f16(acc[mt][nt], afr[mt], bfr[nt]);
        }
    }

#pragma unroll
    for (int mt = 0; mt < 2; mt++) {
#pragma unroll
        for (int half_ = 0; half_ < 2; half_++) {
            int row = bm + wm + mt * 16 + fr + half_ * 8;
#pragma unroll
            for (int nt = 0; nt < 4; nt++) {
                int col = bn + wn + nt * 8 + 2 * fc;
                *(float2*)(Cout + (size_t)row * HIDD + col) = make_float2(
                    acc[mt][nt][half_ * 2 + 0], acc[mt][nt][half_ * 2 + 1]);
            }
        }
    }
}

// ---------------------------------------------------------------------------
// Causal flash attention: fp16 MMA + LDSM, f16x2-exp log2 softmax,
//   rowsum via ones-MMA, warp-uniform rescale skip.
//   q-tile 128 (warp 16 rows), k-tile 64, 4-buffer KV ring (depth 3).
// ---------------------------------------------------------------------------
#define Q_B 16384
#define KV_B 8192
#define ATTN_NBUF 4
#define SMEM_ATTN (Q_B + ATTN_NBUF * 2 * KV_B)   // 81,920 B

__global__ __launch_bounds__(256, 2) void attn_k()
{
    extern __shared__ __align__(16) char smc[];
    const uint32_t sQ = smem_u32(smc);
    const uint32_t sKV = sQ + Q_B;

    const int bh = blockIdx.y;
    const int qt = (gridDim.x - 1) - blockIdx.x;   // heavy tiles first
    const int qstart = qt * 128;
    const __half* Qg = &g_Q[bh][0][0];
    const __half* Kg = &g_K[bh][0][0];
    const __half* Vtg = &g_Vt[bh][0][0];

    const int tid = threadIdx.x;
    const int wq = tid >> 5;
    const int lane = tid & 31;
    const int fr = lane >> 2;
    const int fc = lane & 3;
    const int r0 = wq * 16 + fr, r1 = r0 + 8;

    const int li = lane & 7;
    const int g8 = (lane >> 3) & 1, g16 = lane >> 4;
    const int rowQ = wq * 16 + g8 * 8 + li;
    const uint32_t rowOffQ = (uint32_t)rowQ * 128;
    const int rmQ = rowQ & 7;
    uint32_t rowOffKV[4]; int rmKV[4];
#pragma unroll
    for (int j = 0; j < 4; j++) {
        int r = j * 16 + g16 * 8 + li;
        rowOffKV[j] = (uint32_t)r * 128; rmKV[j] = r & 7;
    }

    auto issue_kv = [&](int jt) {
        int buf = jt % ATTN_NBUF;
        uint32_t sK = sKV + (uint32_t)buf * (2 * KV_B);
        uint32_t sV = sK + KV_B;
        int kstart = jt * 64;
#pragma unroll
        for (int it = 0; it < 2; it++) {
            int chunk = tid + 256 * it;
            int row = chunk >> 3;
            int cc = chunk & 7;
            uint32_t off = (uint32_t)row * 128 +
                           (uint32_t)((cc ^ (row & 7)) << 4);
            cp16(sK + off, Kg + (size_t)(kstart + row) * HD + cc * 8);
            cp16(sV + off, Vtg + (size_t)row * SVLEN + kstart + cc * 8);
        }
    };

    // prologue: (Q + kv0) group, kv1 group, kv2 group
#pragma unroll
    for (int it = 0; it < 4; it++) {
        int chunk = tid + 256 * it;
        int row = chunk >> 3;
        int cc = chunk & 7;
        uint32_t off = (uint32_t)row * 128 + (uint32_t)((cc ^ (row & 7)) << 4);
        cp16(sQ + off, Qg + (size_t)(qstart + row) * HD + cc * 8);
    }
    issue_kv(0); CP_COMMIT();
    issue_kv(1); CP_COMMIT();
    issue_kv(2); CP_COMMIT();      // may overrun jmax; in-bounds (sv=2048)

    float O[8][4];
    float m0 = NEG_INF, m1 = NEG_INF, l0 = 0.f, l1 = 0.f;
#pragma unroll
    for (int nt = 0; nt < 8; nt++)
#pragma unroll
        for (int j = 0; j < 4; j++) O[nt][j] = 0.f;

    uint32_t qfr[4][4];
    const uint32_t bone[2] = {0x3C003C00u, 0x3C003C00u};   // all-ones B frag

    const int jmax = 2 * qt + 1;
    for (int jt = 0; jt <= jmax; jt++) {
        const int kstart = jt * 64;
        CP_WAIT(2);           // tile jt (and Q at jt=0) complete
        __syncthreads();      // all warps finished with buf (jt-1)
        if (jt + 3 <= jmax) issue_kv(jt + 3);
        CP_COMMIT();
        uint32_t Kb = sKV + (uint32_t)(jt % ATTN_NBUF) * (2 * KV_B);
        uint32_t Vb = Kb + KV_B;

        if (jt == 0) {
#pragma unroll
            for (int k16 = 0; k16 < 4; k16++) {
                uint32_t a = sQ + rowOffQ +
                    (uint32_t)((((2 * k16) + g16) ^ rmQ) << 4);
                ldsm_x4(qfr[k16][0], qfr[k16][1], qfr[k16][2], qfr[k16][3], a);
            }
        }

        // ---- S = Q K^T (pre-scaled by scale*log2e) ----
        float s[8][4];
#pragma unroll
        for (int nt = 0; nt < 8; nt++)
#pragma unroll
            for (int j = 0; j < 4; j++) s[nt][j] = 0.f;
#pragma unroll
        for (int k16 = 0; k16 < 4; k16++) {
            uint32_t bfr[8][2];
#pragma unroll
            for (int j = 0; j < 4; j++) {
                uint32_t a = Kb + rowOffKV[j] +
                    (uint32_t)((((2 * k16) + g8) ^ rmKV[j]) << 4);
                ldsm_x4(bfr[2 * j][0], bfr[2 * j][1],
                        bfr[2 * j + 1][0], bfr[2 * j + 1][1], a);
            }
#pragma unroll
            for (int nt = 0; nt < 8; nt++)
                mma_f16(s[nt], qfr[k16], bfr[nt]);
        }

        // causal mask
        if (kstart + 63 > qstart + wq * 16) {
            int gr0 = qstart + r0, gr1 = gr0 + 8;
#pragma unroll
            for (int nt = 0; nt < 8; nt++) {
                int c0 = kstart + nt * 8 + 2 * fc;
                if (c0 > gr0)     s[nt][0] = NEG_INF;
                if (c0 + 1 > gr0) s[nt][1] = NEG_INF;
                if (c0 > gr1)     s[nt][2] = NEG_INF;
                if (c0 + 1 > gr1) s[nt][3] = NEG_INF;
            }
        }

        // ---- max update ----
        float mx0 = NEG_INF, mx1 = NEG_INF;
#pragma unroll
        for (int nt = 0; nt < 8; nt++) {
            mx0 = fmaxf(mx0, fmaxf(s[nt][0], s[nt][1]));
            mx1 = fmaxf(mx1, fmaxf(s[nt][2], s[nt][3]));
        }
        mx0 = fmaxf(mx0, __shfl_xor_sync(0xffffffffu, mx0, 1));
        mx0 = fmaxf(mx0, __shfl_xor_sync(0xffffffffu, mx0, 2));
        mx1 = fmaxf(mx1, __shfl_xor_sync(0xffffffffu, mx1, 1));
        mx1 = fmaxf(mx1, __shfl_xor_sync(0xffffffffu, mx1, 2));
        float newm0 = fmaxf(m0, mx0), newm1 = fmaxf(m1, mx1);
        uint32_t anych = __any_sync(0xffffffffu,
                                    (newm0 > m0) || (newm1 > m1));

        // ---- P = 2^(s-m) straight into PV A-fragments (f16x2 exp) ----
        uint32_t pfr[4][4];
#pragma unroll
        for (int nt = 0; nt < 8; nt++) {
            float f0 = s[nt][0] - newm0;
            float f1 = s[nt][1] - newm0;
            float f2 = s[nt][2] - newm1;
            float f3 = s[nt][3] - newm1;
            int t16 = nt >> 1, hi = nt & 1;
            pfr[t16][hi * 2 + 0] = ex2h2(cvt2h(f1, f0));   // lo=p0, hi=p1
            pfr[t16][hi * 2 + 1] = ex2h2(cvt2h(f3, f2));   // lo=p2, hi=p3
        }

        // ---- rowsum via ones-MMA: every output column == rowsum ----
        float srs[4] = {0.f, 0.f, 0.f, 0.f};
#pragma unroll
        for (int k16 = 0; k16 < 4; k16++)
            mma_f16(srs, pfr[k16], bone);
        float rs0 = srs[0], rs1 = srs[2];

        if (anych) {
            float al0 = ex2(m0 - newm0);
            float al1 = ex2(m1 - newm1);
            l0 = l0 * al0 + rs0; l1 = l1 * al1 + rs1;
            m0 = newm0; m1 = newm1;
#pragma unroll
            for (int nt = 0; nt < 8; nt++) {
                O[nt][0] *= al0; O[nt][1] *= al0;
                O[nt][2] *= al1; O[nt][3] *= al1;
            }
        } else {
            l0 += rs0; l1 += rs1;
        }

        // ---- O += P V (A in regs; B via LDSM from Vts[d][kv]) ----
#pragma unroll
        for (int k16 = 0; k16 < 4; k16++) {
            uint32_t bfr[8][2];
#pragma unroll
            for (int j = 0; j < 4; j++) {
                uint32_t a = Vb + rowOffKV[j] +
                    (uint32_t)((((2 * k16) + g8) ^ rmKV[j]) << 4);
                ldsm_x4(bfr[2 * j][0], bfr[2 * j][1],
                        bfr[2 * j + 1][0], bfr[2 * j + 1][1], a);
            }
#pragma unroll
            for (int nt = 0; nt < 8; nt++)
                mma_f16(O[nt], pfr[k16], bfr[nt]);
        }
    }

    // epilogue: normalize, store natural fp16 into g_Aout
    __half* Ag = &g_Aout[bh][0][0];
    float inv0 = 1.f / l0, inv1 = 1.f / l1;
#pragma unroll
    for (int nt = 0; nt < 8; nt++) {
        int pos = nt * 8 + 2 * fc;
        st_h2(Ag + (size_t)(qstart + r0) * HD + pos,
              O[nt][0] * inv0, O[nt][1] * inv0);
        st_h2(Ag + (size_t)(qstart + r1) * HD + pos,
              O[nt][2] * inv1, O[nt][3] * inv1);
    }
}

// ---------------------------------------------------------------------------
// launch
// ---------------------------------------------------------------------------
extern "C" void kernel_launch(void* const* d_in, const int* in_sizes, int n_in,
                              void* d_out, int out_size)
{
    const float* x  = (const float*)d_in[0];
    const float* Wq = (const float*)d_in[1];
    const float* Wk = (const float*)d_in[2];
    const float* Wv = (const float*)d_in[3];
    const float* Wo = (const float*)d_in[4];
    const float* aq = (const float*)d_in[5];
    const float* ak = (const float*)d_in[6];
    const float* av = (const float*)d_in[7];
    const float* cl = (const float*)d_in[8];
    float* out = (float*)d_out;

    cudaFuncSetAttribute(gemmA_k, cudaFuncAttributeMaxDynamicSharedMemorySize, SMEM_G);
    cudaFuncSetAttribute(gemmO_k, cudaFuncAttributeMaxDynamicSharedMemorySize, SMEM_O);
    cudaFuncSetAttribute(attn_k, cudaFuncAttributeMaxDynamicSharedMemorySize, SMEM_ATTN);

    // fused prologue: weight builds + x rounding, all concurrent
    prep_k<<<dim3(256, 5), 256>>>(x, Wq, Wk, Wv, Wo, aq, ak, av, cl);

    // projections + head mixing (q/k/v via z)
    gemmA_k<<<dim3(NPROJ / 128, MTOK / 128, 3), 256, SMEM_G>>>();

    // causal SDPA over virtual positions
    attn_k<<<dim3(SVLEN / 128, NB * NH), 256, SMEM_ATTN>>>();

    // collapse + output projection (256 CTAs, KC=128)
    gemmO_k<<<dim3(HIDD / 128, MTOK / 64), 256, SMEM_O>>>(out);
}